// round 15
// baseline (speedup 1.0000x reference)
#include <cuda_runtime.h>
#include <cuda_fp16.h>
#include <cstdint>
#include <math.h>

#define NB 2
#define NC 256
#define NPTS 4096
#define NG 8
#define CPG 32
#define NHEADS (NB*NG)
#define BQ 64
#define BK 128
#define NQB (NPTS/BQ)
#define NKB (NPTS/BK)

#define SBIAS  (-12.f)
#define SCLAMP 14.f

// ---------------------------------------------------------------------------
// helpers (base-target safe: sm_80-era mma.sync + cp.async + ldmatrix)
// ---------------------------------------------------------------------------
__device__ __forceinline__ uint32_t ex2_h2(uint32_t a) {
    uint32_t r;
    asm("ex2.approx.f16x2 %0, %1;" : "=r"(r) : "r"(a));
    return r;
}
__device__ __forceinline__ uint32_t hmin2(uint32_t a, uint32_t b) {
    uint32_t r;
    asm("min.f16x2 %0, %1, %2;" : "=r"(r) : "r"(a), "r"(b));
    return r;
}
__device__ __forceinline__ uint32_t hadd2(uint32_t a, uint32_t b) {
    uint32_t r;
    asm("add.rn.f16x2 %0, %1, %2;" : "=r"(r) : "r"(a), "r"(b));
    return r;
}
// fp32-accumulate mma (PV)
__device__ __forceinline__ void mma_fp16(float* d, const uint32_t* a,
                                         uint32_t b0, uint32_t b1) {
    asm volatile(
        "mma.sync.aligned.m16n8k16.row.col.f32.f16.f16.f32 "
        "{%0,%1,%2,%3}, {%4,%5,%6,%7}, {%8,%9}, {%0,%1,%2,%3};"
        : "+f"(d[0]), "+f"(d[1]), "+f"(d[2]), "+f"(d[3])
        : "r"(a[0]), "r"(a[1]), "r"(a[2]), "r"(a[3]), "r"(b0), "r"(b1));
}
// fp16-accumulate mma (S) — D comes out as packed f16x2 pairs
__device__ __forceinline__ void mma_h16(uint32_t* c, const uint32_t* a,
                                        uint32_t b0, uint32_t b1) {
    asm volatile(
        "mma.sync.aligned.m16n8k16.row.col.f16.f16.f16.f16 "
        "{%0,%1}, {%2,%3,%4,%5}, {%6,%7}, {%0,%1};"
        : "+r"(c[0]), "+r"(c[1])
        : "r"(a[0]), "r"(a[1]), "r"(a[2]), "r"(a[3]), "r"(b0), "r"(b1));
}
__device__ __forceinline__ uint32_t hmul2(uint32_t a, uint32_t b) {
    uint32_t r;
    asm("mul.rn.f16x2 %0, %1, %2;" : "=r"(r) : "r"(a), "r"(b));
    return r;
}
__device__ __forceinline__ void ldsm4(uint32_t* r, uint32_t addr) {
    asm volatile(
        "ldmatrix.sync.aligned.m8n8.x4.shared.b16 {%0,%1,%2,%3}, [%4];"
        : "=r"(r[0]), "=r"(r[1]), "=r"(r[2]), "=r"(r[3]) : "r"(addr));
}
__device__ __forceinline__ void cp16(uint32_t smem_dst, const void* gsrc) {
    asm volatile("cp.async.cg.shared.global [%0], [%1], 16;"
                 :: "r"(smem_dst), "l"(gsrc));
}
#define CP_COMMIT() asm volatile("cp.async.commit_group;" ::: "memory")
#define CP_WAIT_ALL() asm volatile("cp.async.wait_all;" ::: "memory")

// ---------------------------------------------------------------------------
// scratch: x fp16 [head][n][d], v = elu(x) fp16 [head][d][n]
// g_fpart: GN partials [b][group c][gh][qb][2]
// ---------------------------------------------------------------------------
__device__ __half  g_x[NHEADS*NPTS*CPG];
__device__ __half  g_v[NHEADS*CPG*NPTS];
__device__ float   g_fpart[NB*32*NG*NQB*2];

// ---------------------------------------------------------------------------
// Kernel 1: grouped 1x1 conv + bias (fp32 elu; fastest measured variant).
// Writes x fp16 transposed [n][d] (SMEM transpose) and elu(x) fp16 [d][n].
// ---------------------------------------------------------------------------
__global__ void __launch_bounds__(128) conv_kernel(
    const float* __restrict__ points,
    const float* __restrict__ conv_w,
    const float* __restrict__ conv_b)
{
    __shared__ float ws[CPG*CPG];
    __shared__ float bs[CPG];
    __shared__ uint32_t xs[64*17];
    const int h = blockIdx.y;
    const int b = h >> 3, g = h & 7;
    const int t = threadIdx.x;
    for (int i = t; i < CPG*CPG; i += 128) ws[i] = conv_w[g*CPG*CPG + i];
    if (t < CPG) bs[t] = conv_b[g*CPG + t];
    __syncthreads();

    const int pt = t & 63, half = t >> 6;
    const int n = blockIdx.x*64 + pt;
    const float* base = points + (b*NC + g*CPG)*NPTS + n;
    float p[CPG];
    #pragma unroll
    for (int j = 0; j < CPG; j++) p[j] = base[j*NPTS];

    __half* vo = g_v + h*CPG*NPTS + n;
    float prev = 0.f;
    #pragma unroll 4
    for (int i = 0; i < 16; i++) {
        const int ch = half*16 + i;
        float a = bs[ch];
        #pragma unroll
        for (int j = 0; j < CPG; j++) a = fmaf(ws[ch*CPG + j], p[j], a);
        float e = a > 0.f ? a : (__expf(a) - 1.f);
        vo[ch*NPTS] = __float2half_rn(e);
        if (i & 1) {
            __half2 hp = __floats2half2_rn(prev, a);
            xs[pt*17 + half*8 + (i >> 1)] = *(uint32_t*)&hp;
        } else prev = a;
    }
    __syncthreads();
    uint32_t* gb = (uint32_t*)g_x + ((size_t)h*NPTS + blockIdx.x*64)*16;
    #pragma unroll
    for (int j = 0; j < 8; j++) {
        int m = j*128 + t;
        gb[m] = xs[(m >> 4)*17 + (m & 15)];
    }
}

// ---------------------------------------------------------------------------
// Kernel 2: flash attention, BQ=64, 128-thread CTAs (warp owns 16 q rows).
// Grid (64,16)=1024 CTAs -> 6.92 quanta/SM, ~1% pipe-balance loss (vs 15.6%
// at 256 CTAs). 5 CTAs/SM by smem. S fp16-acc mma -> clamp+ex2 f16x2; PV
// fp32-acc; ldmatrix everywhere; cp.async double-buffered K/V; fused GN stats.
// ---------------------------------------------------------------------------
__global__ void __launch_bounds__(128, 5) flash_kernel(
    const float* __restrict__ points, float* __restrict__ out)
{
    __shared__ __align__(16) __half  Kt[2][128][40];   // [buf][k][d]
    __shared__ __align__(16) __half  Vs[2][32][136];   // [buf][c][k]
    __shared__ float   SL[64];
    __shared__ float   PS[4][8][4], PS2[4][8][4];      // [w][g][cidx]

    const int t = threadIdx.x, w = t >> 5, lane = t & 31;
    const int g = lane >> 2, qt = lane & 3;
    const int h = blockIdx.y, b = h >> 3, gh = h & 7;
    const int q0 = blockIdx.x * BQ;
    const __half* __restrict__ xh = g_x + (size_t)h*NPTS*CPG;
    const __half* __restrict__ vh = g_v + h*CPG*NPTS;

    __half2 c2 = __float2half2_rn(SCLAMP);
    const uint32_t clampv = *(uint32_t*)&c2;
    __half2 b2 = __float2half2_rn(SBIAS);
    const uint32_t sbias2 = *(uint32_t*)&b2;

    const uint32_t ktb0 = (uint32_t)__cvta_generic_to_shared(&Kt[0][0][0]);
    const uint32_t ktb1 = (uint32_t)__cvta_generic_to_shared(&Kt[1][0][0]);
    const uint32_t vsb0 = (uint32_t)__cvta_generic_to_shared(&Vs[0][0][0]);
    const uint32_t vsb1 = (uint32_t)__cvta_generic_to_shared(&Vs[1][0][0]);
    const uint32_t koff2 = ((lane & 7)*40 + (lane >> 3)*8) * 2;
    const uint32_t voff2 = (((lane & 7) + ((lane >> 3) & 1)*8)*136 + (lane >> 4)*8) * 2;

    // ---- Q fragments fp16, scaled by log2e/sqrt(32) ----
    uint32_t qf[2][4];
    {
        const uint32_t* xq = (const uint32_t*)xh;
        __half2 s2h = __float2half2_rn(0.25504526770237225f);
        uint32_t sc = *(uint32_t*)&s2h;
        const int qr = q0 + 16*w + g;
        #pragma unroll
        for (int ds = 0; ds < 2; ds++) {
            qf[ds][0] = hmul2(xq[(size_t)qr*16     + ds*8 + qt    ], sc);
            qf[ds][1] = hmul2(xq[(size_t)(qr+8)*16 + ds*8 + qt    ], sc);
            qf[ds][2] = hmul2(xq[(size_t)qr*16     + ds*8 + qt + 4], sc);
            qf[ds][3] = hmul2(xq[(size_t)(qr+8)*16 + ds*8 + qt + 4], sc);
        }
    }

    float O[2][2][4];   // [cm][qh][e]
    #pragma unroll
    for (int i = 0; i < 2; i++)
        #pragma unroll
        for (int j = 0; j < 2; j++)
            #pragma unroll
            for (int e = 0; e < 4; e++) O[i][j][e] = 0.f;
    float lsum[2] = {0.f, 0.f};

    // fill: K = 512 16B chunks (4/thread), V = 512 16B chunks (4/thread)
    // ---- prefetch tile 0 ----
    {
        #pragma unroll
        for (int j = 0; j < 4; j++) {
            int c = t + j*128;
            int krow = c >> 2, kpart = c & 3;
            cp16((uint32_t)__cvta_generic_to_shared(&Kt[0][krow][kpart*8]),
                 xh + (size_t)krow*32 + kpart*8);
            int vrow = c >> 4, vpart = c & 15;
            cp16((uint32_t)__cvta_generic_to_shared(&Vs[0][vrow][vpart*8]),
                 vh + vrow*NPTS + vpart*8);
        }
        CP_COMMIT();
    }

    for (int kb = 0; kb < NKB; kb++) {
        const int buf = kb & 1;
        const uint32_t ktb = buf ? ktb1 : ktb0;
        const uint32_t vsb = buf ? vsb1 : vsb0;
        CP_WAIT_ALL();
        __syncthreads();
        if (kb + 1 < NKB) {
            const int k0n = (kb + 1) * BK;
            #pragma unroll
            for (int j = 0; j < 4; j++) {
                int c = t + j*128;
                int krow = c >> 2, kpart = c & 3;
                cp16((uint32_t)__cvta_generic_to_shared(&Kt[buf ^ 1][krow][kpart*8]),
                     xh + (size_t)(k0n + krow)*32 + kpart*8);
                int vrow = c >> 4, vpart = c & 15;
                cp16((uint32_t)__cvta_generic_to_shared(&Vs[buf ^ 1][vrow][vpart*8]),
                     vh + vrow*NPTS + k0n + vpart*8);
            }
            CP_COMMIT();
        }

        #pragma unroll
        for (int ch = 0; ch < 4; ch++) {
            uint32_t Plo[4], Phi[4];
            #pragma unroll
            for (int hf = 0; hf < 2; hf++) {
                const int kk = ch*32 + hf*16;
                // hoist V frags (independent of P) to overlap with S chain
                uint32_t av[2][4];
                #pragma unroll
                for (int cm = 0; cm < 2; cm++)
                    ldsm4(av[cm], vsb + (uint32_t)(16*cm*136 + kk)*2 + voff2);
                #pragma unroll
                for (int nti = 0; nti < 2; nti++) {
                    const int kbase = ch*32 + (hf*2 + nti)*8;
                    uint32_t bk[4];
                    ldsm4(bk, ktb + (uint32_t)kbase*80 + koff2);
                    uint32_t accp[2] = {sbias2, sbias2};
                    mma_h16(accp, qf[0], bk[0], bk[1]);
                    mma_h16(accp, qf[1], bk[2], bk[3]);
                    Plo[hf*2 + nti] = ex2_h2(hmin2(accp[0], clampv));
                    Phi[hf*2 + nti] = ex2_h2(hmin2(accp[1], clampv));
                }
                #pragma unroll
                for (int cm = 0; cm < 2; cm++) {
                    mma_fp16(O[cm][0], av[cm], Plo[hf*2], Plo[hf*2+1]);
                    mma_fp16(O[cm][1], av[cm], Phi[hf*2], Phi[hf*2+1]);
                }
            }
            uint32_t tl = hadd2(hadd2(Plo[0], Plo[1]), hadd2(Plo[2], Plo[3]));
            uint32_t th = hadd2(hadd2(Phi[0], Phi[1]), hadd2(Phi[2], Phi[3]));
            float2 fl = __half22float2(*(__half2*)&tl);
            float2 fh = __half22float2(*(__half2*)&th);
            lsum[0] += fl.x + fl.y;
            lsum[1] += fh.x + fh.y;
        }
    }

    // ---- l[q] reduction over the quad ----
    lsum[0] += __shfl_xor_sync(0xffffffffu, lsum[0], 1);
    lsum[0] += __shfl_xor_sync(0xffffffffu, lsum[0], 2);
    lsum[1] += __shfl_xor_sync(0xffffffffu, lsum[1], 1);
    lsum[1] += __shfl_xor_sync(0xffffffffu, lsum[1], 2);
    __syncthreads();
    if (qt == 0) {
        SL[w*16 + g]     = lsum[0];
        SL[w*16 + 8 + g] = lsum[1];
    }
    __syncthreads();

    // ---- epilogue: divide by l, channel shuffle, residual + GN partials ----
    float cs[4] = {0.f, 0.f, 0.f, 0.f}, cs2[4] = {0.f, 0.f, 0.f, 0.f};
    #pragma unroll
    for (int qh = 0; qh < 2; qh++) {
        const int qr = qh*8 + 2*qt;
        const float i0 = 1.f / SL[w*16 + qr];
        const float i1 = 1.f / SL[w*16 + qr + 1];
        const int q = q0 + 16*w + qr;
        #pragma unroll
        for (int cm = 0; cm < 2; cm++) {
            const int c = 16*cm + g;
            int idx = (b*NC + c*NG + gh)*NPTS + q;
            float2 r = *(const float2*)(points + idx);
            float2 o;
            o.x = O[cm][qh][0]*i0 + r.x;
            o.y = O[cm][qh][1]*i1 + r.y;
            *(float2*)(out + idx) = o;
            cs[2*cm]  += o.x + o.y;
            cs2[2*cm] += o.x*o.x + o.y*o.y;
            int idx2 = idx + 8*NG*NPTS;
            float2 r2 = *(const float2*)(points + idx2);
            float2 o2;
            o2.x = O[cm][qh][2]*i0 + r2.x;
            o2.y = O[cm][qh][3]*i1 + r2.y;
            *(float2*)(out + idx2) = o2;
            cs[2*cm+1]  += o2.x + o2.y;
            cs2[2*cm+1] += o2.x*o2.x + o2.y*o2.y;
        }
    }
    #pragma unroll
    for (int i = 0; i < 4; i++) {
        cs[i]  += __shfl_xor_sync(0xffffffffu, cs[i], 1);
        cs[i]  += __shfl_xor_sync(0xffffffffu, cs[i], 2);
        cs2[i] += __shfl_xor_sync(0xffffffffu, cs2[i], 1);
        cs2[i] += __shfl_xor_sync(0xffffffffu, cs2[i], 2);
    }
    if (qt == 0) {
        #pragma unroll
        for (int i = 0; i < 4; i++) { PS[w][g][i] = cs[i]; PS2[w][g][i] = cs2[i]; }
    }
    __syncthreads();
    if (t < 32) {                       // 8 groups x 4 cidx = 32 entries
        const int gg = t >> 2, ci = t & 3;
        float s = 0.f, s2 = 0.f;
        #pragma unroll
        for (int ww = 0; ww < 4; ww++) { s += PS[ww][gg][ci]; s2 += PS2[ww][gg][ci]; }
        const int c = gg + 8*ci;        // GN group index (0..31)
        float* fp = g_fpart + ((((b*32 + c)*NG + gh)*NQB + blockIdx.x)*2);
        fp[0] = s; fp[1] = s2;
    }
}

// ---------------------------------------------------------------------------
// Kernel 3: GN apply. 512 CTAs = (b, group, slice). Deterministic reduction
// of the group's 512 flash partials (2/thread + smem tree), normalize in place.
// ---------------------------------------------------------------------------
__global__ void __launch_bounds__(256) gn_apply(
    float* __restrict__ out,
    const float* __restrict__ gn_w,
    const float* __restrict__ gn_b)
{
    __shared__ float rs[256], rs2[256];
    const int grpid = blockIdx.x >> 3, slice = blockIdx.x & 7;
    const int b = grpid >> 5, grp = grpid & 31;
    const int ch = grp*8 + slice;
    float* base = out + ((b*NC + ch)*NPTS);
    const int t = threadIdx.x;

    const float* fp = g_fpart + (size_t)grpid*NG*NQB*2;   // 512 pairs
    rs[t]  = fp[2*t]       + fp[2*(t + 256)];
    rs2[t] = fp[2*t + 1]   + fp[2*(t + 256) + 1];
    __syncthreads();
    for (int o = 128; o; o >>= 1) {
        if (t < o) { rs[t] += rs[t+o]; rs2[t] += rs2[t+o]; }
        __syncthreads();
    }
    const float inv = 1.f / (float)(8*NPTS);
    float mean = rs[0] * inv;
    float var  = rs2[0] * inv - mean*mean;
    float rstd = rsqrtf(var + 1e-5f);
    float wv = gn_w[ch] * rstd;
    float bv = gn_b[ch] - mean * wv;

    #pragma unroll
    for (int j = 0; j < 4; j++) {
        float4 v = *(const float4*)(base + j*1024 + t*4);
        v.x = v.x*wv + bv; v.y = v.y*wv + bv;
        v.z = v.z*wv + bv; v.w = v.w*wv + bv;
        *(float4*)(base + j*1024 + t*4) = v;
    }
}

// ---------------------------------------------------------------------------
extern "C" void kernel_launch(void* const* d_in, const int* in_sizes, int n_in,
                              void* d_out, int out_size)
{
    const float* points = (const float*)d_in[0];
    const float* conv_w = (const float*)d_in[1];
    const float* conv_b = (const float*)d_in[2];
    const float* gn_w   = (const float*)d_in[3];
    const float* gn_b   = (const float*)d_in[4];
    float* out = (float*)d_out;

    conv_kernel<<<dim3(NPTS/64, NHEADS), 128>>>(points, conv_w, conv_b);
    flash_kernel<<<dim3(NQB, NHEADS), 128>>>(points, out);
    gn_apply<<<512, 256>>>(out, gn_w, gn_b);
}

// round 16
// speedup vs baseline: 1.0291x; 1.0291x over previous
#include <cuda_runtime.h>
#include <cuda_fp16.h>
#include <cstdint>
#include <math.h>

#define NB 2
#define NC 256
#define NPTS 4096
#define NG 8
#define CPG 32
#define NHEADS (NB*NG)
#define BQ 256
#define BK 256
#define NQB (NPTS/BQ)
#define NKB (NPTS/BK)

#define SBIAS  (-12.f)
#define SCLAMP 14.f

// ---------------------------------------------------------------------------
// helpers (base-target safe: sm_80-era mma.sync + cp.async + ldmatrix)
// ---------------------------------------------------------------------------
__device__ __forceinline__ uint32_t ex2_h2(uint32_t a) {
    uint32_t r;
    asm("ex2.approx.f16x2 %0, %1;" : "=r"(r) : "r"(a));
    return r;
}
__device__ __forceinline__ uint32_t hmin2(uint32_t a, uint32_t b) {
    uint32_t r;
    asm("min.f16x2 %0, %1, %2;" : "=r"(r) : "r"(a), "r"(b));
    return r;
}
__device__ __forceinline__ uint32_t hadd2(uint32_t a, uint32_t b) {
    uint32_t r;
    asm("add.rn.f16x2 %0, %1, %2;" : "=r"(r) : "r"(a), "r"(b));
    return r;
}
// fp32-accumulate mma (PV)
__device__ __forceinline__ void mma_fp16(float* d, const uint32_t* a,
                                         uint32_t b0, uint32_t b1) {
    asm volatile(
        "mma.sync.aligned.m16n8k16.row.col.f32.f16.f16.f32 "
        "{%0,%1,%2,%3}, {%4,%5,%6,%7}, {%8,%9}, {%0,%1,%2,%3};"
        : "+f"(d[0]), "+f"(d[1]), "+f"(d[2]), "+f"(d[3])
        : "r"(a[0]), "r"(a[1]), "r"(a[2]), "r"(a[3]), "r"(b0), "r"(b1));
}
// fp16-accumulate mma (S) — D comes out as packed f16x2 pairs
__device__ __forceinline__ void mma_h16(uint32_t* c, const uint32_t* a,
                                        uint32_t b0, uint32_t b1) {
    asm volatile(
        "mma.sync.aligned.m16n8k16.row.col.f16.f16.f16.f16 "
        "{%0,%1}, {%2,%3,%4,%5}, {%6,%7}, {%0,%1};"
        : "+r"(c[0]), "+r"(c[1])
        : "r"(a[0]), "r"(a[1]), "r"(a[2]), "r"(a[3]), "r"(b0), "r"(b1));
}
__device__ __forceinline__ uint32_t hmul2(uint32_t a, uint32_t b) {
    uint32_t r;
    asm("mul.rn.f16x2 %0, %1, %2;" : "=r"(r) : "r"(a), "r"(b));
    return r;
}
__device__ __forceinline__ void ldsm4(uint32_t* r, uint32_t addr) {
    asm volatile(
        "ldmatrix.sync.aligned.m8n8.x4.shared.b16 {%0,%1,%2,%3}, [%4];"
        : "=r"(r[0]), "=r"(r[1]), "=r"(r[2]), "=r"(r[3]) : "r"(addr));
}
__device__ __forceinline__ void cp16(uint32_t smem_dst, const void* gsrc) {
    asm volatile("cp.async.cg.shared.global [%0], [%1], 16;"
                 :: "r"(smem_dst), "l"(gsrc));
}
#define CP_COMMIT() asm volatile("cp.async.commit_group;" ::: "memory")
#define CP_WAIT_ALL() asm volatile("cp.async.wait_all;" ::: "memory")

// ---------------------------------------------------------------------------
// scratch: x fp16 [head][n][d], v = elu(x) fp16 [head][d][n]
// g_fpart: GN partials [b][group c][gh][qb][2]
// ---------------------------------------------------------------------------
__device__ __half  g_x[NHEADS*NPTS*CPG];
__device__ __half  g_v[NHEADS*CPG*NPTS];
__device__ float   g_fpart[NB*32*NG*NQB*2];

// ---------------------------------------------------------------------------
// Kernel 1: grouped 1x1 conv + bias (fp32 elu; fastest measured variant).
// Writes x fp16 transposed [n][d] (SMEM transpose) and elu(x) fp16 [d][n].
// ---------------------------------------------------------------------------
__global__ void __launch_bounds__(128) conv_kernel(
    const float* __restrict__ points,
    const float* __restrict__ conv_w,
    const float* __restrict__ conv_b)
{
    __shared__ float ws[CPG*CPG];
    __shared__ float bs[CPG];
    __shared__ uint32_t xs[64*17];
    const int h = blockIdx.y;
    const int b = h >> 3, g = h & 7;
    const int t = threadIdx.x;
    for (int i = t; i < CPG*CPG; i += 128) ws[i] = conv_w[g*CPG*CPG + i];
    if (t < CPG) bs[t] = conv_b[g*CPG + t];
    __syncthreads();

    const int pt = t & 63, half = t >> 6;
    const int n = blockIdx.x*64 + pt;
    const float* base = points + (b*NC + g*CPG)*NPTS + n;
    float p[CPG];
    #pragma unroll
    for (int j = 0; j < CPG; j++) p[j] = base[j*NPTS];

    __half* vo = g_v + h*CPG*NPTS + n;
    float prev = 0.f;
    #pragma unroll 4
    for (int i = 0; i < 16; i++) {
        const int ch = half*16 + i;
        float a = bs[ch];
        #pragma unroll
        for (int j = 0; j < CPG; j++) a = fmaf(ws[ch*CPG + j], p[j], a);
        float e = a > 0.f ? a : (__expf(a) - 1.f);
        vo[ch*NPTS] = __float2half_rn(e);
        if (i & 1) {
            __half2 hp = __floats2half2_rn(prev, a);
            xs[pt*17 + half*8 + (i >> 1)] = *(uint32_t*)&hp;
        } else prev = a;
    }
    __syncthreads();
    uint32_t* gb = (uint32_t*)g_x + ((size_t)h*NPTS + blockIdx.x*64)*16;
    #pragma unroll
    for (int j = 0; j < 8; j++) {
        int m = j*128 + t;
        gb[m] = xs[(m >> 4)*17 + (m & 15)];
    }
}

// ---------------------------------------------------------------------------
// Kernel 2: flash attention, BQ=256, BK=256 (16 ktiles: half the syncs and
// prefetch batches of BK=128, identical total fill bytes). S fp16-acc mma ->
// clamp+ex2 f16x2 packed; PV fp32-acc; ldmatrix; cp.async double-buffered;
// fused GN-stats epilogue. grid (16,16)=256 CTAs, 2/SM, single wave.
// ---------------------------------------------------------------------------
__global__ void __launch_bounds__(256, 2) flash_kernel(
    const float* __restrict__ points, float* __restrict__ out)
{
    __shared__ __align__(16) __half  Kt[2][256][40];   // [buf][k][d]
    __shared__ __align__(16) __half  Vs[2][32][264];   // [buf][c][k]
    __shared__ float   SL[256];
    __shared__ float   PS[8][8][4], PS2[8][8][4];      // [w][g][cidx]

    const int t = threadIdx.x, w = t >> 5, lane = t & 31;
    const int g = lane >> 2, qt = lane & 3;
    const int h = blockIdx.y, b = h >> 3, gh = h & 7;
    const int q0 = blockIdx.x * BQ;
    const __half* __restrict__ xh = g_x + (size_t)h*NPTS*CPG;
    const __half* __restrict__ vh = g_v + h*CPG*NPTS;

    __half2 c2 = __float2half2_rn(SCLAMP);
    const uint32_t clampv = *(uint32_t*)&c2;
    __half2 b2 = __float2half2_rn(SBIAS);
    const uint32_t sbias2 = *(uint32_t*)&b2;

    const uint32_t ktb0 = (uint32_t)__cvta_generic_to_shared(&Kt[0][0][0]);
    const uint32_t ktb1 = (uint32_t)__cvta_generic_to_shared(&Kt[1][0][0]);
    const uint32_t vsb0 = (uint32_t)__cvta_generic_to_shared(&Vs[0][0][0]);
    const uint32_t vsb1 = (uint32_t)__cvta_generic_to_shared(&Vs[1][0][0]);
    const uint32_t koff2 = ((lane & 7)*40 + (lane >> 3)*8) * 2;
    const uint32_t voff2 = (((lane & 7) + ((lane >> 3) & 1)*8)*264 + (lane >> 4)*8) * 2;

    // ---- Q fragments fp16, scaled by log2e/sqrt(32) ----
    uint32_t qf[2][2][4];
    {
        const uint32_t* xq = (const uint32_t*)xh;
        __half2 s2h = __float2half2_rn(0.25504526770237225f);
        uint32_t sc = *(uint32_t*)&s2h;
        #pragma unroll
        for (int qs = 0; qs < 2; qs++) {
            const int qr = q0 + 32*w + 16*qs + g;
            #pragma unroll
            for (int ds = 0; ds < 2; ds++) {
                qf[qs][ds][0] = hmul2(xq[(size_t)qr*16     + ds*8 + qt    ], sc);
                qf[qs][ds][1] = hmul2(xq[(size_t)(qr+8)*16 + ds*8 + qt    ], sc);
                qf[qs][ds][2] = hmul2(xq[(size_t)qr*16     + ds*8 + qt + 4], sc);
                qf[qs][ds][3] = hmul2(xq[(size_t)(qr+8)*16 + ds*8 + qt + 4], sc);
            }
        }
    }

    float O[2][2][2][4];
    #pragma unroll
    for (int a = 0; a < 2; a++)
        #pragma unroll
        for (int i = 0; i < 2; i++)
            #pragma unroll
            for (int j = 0; j < 2; j++)
                #pragma unroll
                for (int e = 0; e < 4; e++) O[a][i][j][e] = 0.f;
    float lsum[2][2] = {{0.f, 0.f}, {0.f, 0.f}};

    // fill decomposition: K tile = 256x32 halves = 1024 16B chunks (4/thread)
    //                     V tile = 32x256 halves = 1024 16B chunks (4/thread)
    // ---- prefetch tile 0 ----
    {
        #pragma unroll
        for (int j = 0; j < 4; j++) {
            int c = t + j*256;
            int krow = c >> 2, kpart = c & 3;
            cp16((uint32_t)__cvta_generic_to_shared(&Kt[0][krow][kpart*8]),
                 xh + (size_t)krow*32 + kpart*8);
            int vrow = c >> 5, vpart = c & 31;
            cp16((uint32_t)__cvta_generic_to_shared(&Vs[0][vrow][vpart*8]),
                 vh + vrow*NPTS + vpart*8);
        }
        CP_COMMIT();
    }

    for (int kb = 0; kb < NKB; kb++) {
        const int buf = kb & 1;
        const uint32_t ktb = buf ? ktb1 : ktb0;
        const uint32_t vsb = buf ? vsb1 : vsb0;
        CP_WAIT_ALL();
        __syncthreads();
        if (kb + 1 < NKB) {
            const int k0n = (kb + 1) * BK;
            #pragma unroll
            for (int j = 0; j < 4; j++) {
                int c = t + j*256;
                int krow = c >> 2, kpart = c & 3;
                cp16((uint32_t)__cvta_generic_to_shared(&Kt[buf ^ 1][krow][kpart*8]),
                     xh + (size_t)(k0n + krow)*32 + kpart*8);
                int vrow = c >> 5, vpart = c & 31;
                cp16((uint32_t)__cvta_generic_to_shared(&Vs[buf ^ 1][vrow][vpart*8]),
                     vh + vrow*NPTS + k0n + vpart*8);
            }
            CP_COMMIT();
        }

        #pragma unroll
        for (int ch = 0; ch < 8; ch++) {          // 8 chunks of 32 k-cols
            uint32_t Plo[2][4], Phi[2][4];
            #pragma unroll
            for (int hf = 0; hf < 2; hf++) {
                const int kk = ch*32 + hf*16;
                uint32_t av[2][4];
                #pragma unroll
                for (int cm = 0; cm < 2; cm++)
                    ldsm4(av[cm], vsb + (uint32_t)(16*cm*264 + kk)*2 + voff2);
                #pragma unroll
                for (int nti = 0; nti < 2; nti++) {
                    const int kbase = ch*32 + (hf*2 + nti)*8;
                    uint32_t bk[4];
                    ldsm4(bk, ktb + (uint32_t)kbase*80 + koff2);
                    #pragma unroll
                    for (int qs = 0; qs < 2; qs++) {
                        uint32_t accp[2] = {sbias2, sbias2};
                        mma_h16(accp, qf[qs][0], bk[0], bk[1]);
                        mma_h16(accp, qf[qs][1], bk[2], bk[3]);
                        Plo[qs][hf*2 + nti] = ex2_h2(hmin2(accp[0], clampv));
                        Phi[qs][hf*2 + nti] = ex2_h2(hmin2(accp[1], clampv));
                    }
                }
                #pragma unroll
                for (int cm = 0; cm < 2; cm++) {
                    #pragma unroll
                    for (int qs = 0; qs < 2; qs++) {
                        mma_fp16(O[qs][cm][0], av[cm], Plo[qs][hf*2], Plo[qs][hf*2+1]);
                        mma_fp16(O[qs][cm][1], av[cm], Phi[qs][hf*2], Phi[qs][hf*2+1]);
                    }
                }
            }
            #pragma unroll
            for (int qs = 0; qs < 2; qs++) {
                uint32_t tl = hadd2(hadd2(Plo[qs][0], Plo[qs][1]),
                                    hadd2(Plo[qs][2], Plo[qs][3]));
                uint32_t th = hadd2(hadd2(Phi[qs][0], Phi[qs][1]),
                                    hadd2(Phi[qs][2], Phi[qs][3]));
                float2 fl = __half22float2(*(__half2*)&tl);
                float2 fh = __half22float2(*(__half2*)&th);
                lsum[qs][0] += fl.x + fl.y;
                lsum[qs][1] += fh.x + fh.y;
            }
        }
    }

    // ---- l[q] reduction over the quad ----
    #pragma unroll
    for (int qs = 0; qs < 2; qs++) {
        lsum[qs][0] += __shfl_xor_sync(0xffffffffu, lsum[qs][0], 1);
        lsum[qs][0] += __shfl_xor_sync(0xffffffffu, lsum[qs][0], 2);
        lsum[qs][1] += __shfl_xor_sync(0xffffffffu, lsum[qs][1], 1);
        lsum[qs][1] += __shfl_xor_sync(0xffffffffu, lsum[qs][1], 2);
    }
    __syncthreads();
    if (qt == 0) {
        #pragma unroll
        for (int qs = 0; qs < 2; qs++) {
            SL[w*32 + 16*qs + g]     = lsum[qs][0];
            SL[w*32 + 16*qs + 8 + g] = lsum[qs][1];
        }
    }
    __syncthreads();

    // ---- epilogue: divide by l, channel shuffle, residual + GN partials ----
    float cs[4] = {0.f, 0.f, 0.f, 0.f}, cs2[4] = {0.f, 0.f, 0.f, 0.f};
    #pragma unroll
    for (int qs = 0; qs < 2; qs++) {
        #pragma unroll
        for (int qh = 0; qh < 2; qh++) {
            const int qr = 16*qs + qh*8 + 2*qt;
            const float i0 = 1.f / SL[w*32 + qr];
            const float i1 = 1.f / SL[w*32 + qr + 1];
            const int q = q0 + 32*w + qr;
            #pragma unroll
            for (int cm = 0; cm < 2; cm++) {
                const int c = 16*cm + g;
                int idx = (b*NC + c*NG + gh)*NPTS + q;
                float2 r = *(const float2*)(points + idx);
                float2 o;
                o.x = O[qs][cm][qh][0]*i0 + r.x;
                o.y = O[qs][cm][qh][1]*i1 + r.y;
                *(float2*)(out + idx) = o;
                cs[2*cm]  += o.x + o.y;
                cs2[2*cm] += o.x*o.x + o.y*o.y;
                int idx2 = idx + 8*NG*NPTS;
                float2 r2 = *(const float2*)(points + idx2);
                float2 o2;
                o2.x = O[qs][cm][qh][2]*i0 + r2.x;
                o2.y = O[qs][cm][qh][3]*i1 + r2.y;
                *(float2*)(out + idx2) = o2;
                cs[2*cm+1]  += o2.x + o2.y;
                cs2[2*cm+1] += o2.x*o2.x + o2.y*o2.y;
            }
        }
    }
    #pragma unroll
    for (int i = 0; i < 4; i++) {
        cs[i]  += __shfl_xor_sync(0xffffffffu, cs[i], 1);
        cs[i]  += __shfl_xor_sync(0xffffffffu, cs[i], 2);
        cs2[i] += __shfl_xor_sync(0xffffffffu, cs2[i], 1);
        cs2[i] += __shfl_xor_sync(0xffffffffu, cs2[i], 2);
    }
    if (qt == 0) {
        #pragma unroll
        for (int i = 0; i < 4; i++) { PS[w][g][i] = cs[i]; PS2[w][g][i] = cs2[i]; }
    }
    __syncthreads();
    if (t < 32) {                       // 8 groups x 4 cidx = 32 entries
        const int gg = t >> 2, ci = t & 3;
        float s = 0.f, s2 = 0.f;
        #pragma unroll
        for (int ww = 0; ww < 8; ww++) { s += PS[ww][gg][ci]; s2 += PS2[ww][gg][ci]; }
        const int c = gg + 8*ci;        // GN group index (0..31)
        float* fp = g_fpart + ((((b*32 + c)*NG + gh)*NQB + blockIdx.x)*2);
        fp[0] = s; fp[1] = s2;
    }
}

// ---------------------------------------------------------------------------
// Kernel 3: GN apply. 512 CTAs = (b, group, slice). Deterministic reduction
// of the group's 128 flash partials (smem tree), then normalize in place.
// ---------------------------------------------------------------------------
__global__ void __launch_bounds__(256) gn_apply(
    float* __restrict__ out,
    const float* __restrict__ gn_w,
    const float* __restrict__ gn_b)
{
    __shared__ float rs[128], rs2[128];
    const int grpid = blockIdx.x >> 3, slice = blockIdx.x & 7;
    const int b = grpid >> 5, grp = grpid & 31;
    const int ch = grp*8 + slice;
    float* base = out + ((b*NC + ch)*NPTS);
    const int t = threadIdx.x;

    const float* fp = g_fpart + (size_t)grpid*NG*NQB*2;
    if (t < 128) { rs[t] = fp[2*t]; rs2[t] = fp[2*t + 1]; }
    __syncthreads();
    for (int o = 64; o; o >>= 1) {
        if (t < o) { rs[t] += rs[t+o]; rs2[t] += rs2[t+o]; }
        __syncthreads();
    }
    const float inv = 1.f / (float)(8*NPTS);
    float mean = rs[0] * inv;
    float var  = rs2[0] * inv - mean*mean;
    float rstd = rsqrtf(var + 1e-5f);
    float wv = gn_w[ch] * rstd;
    float bv = gn_b[ch] - mean * wv;

    #pragma unroll
    for (int j = 0; j < 4; j++) {
        float4 v = *(const float4*)(base + j*1024 + t*4);
        v.x = v.x*wv + bv; v.y = v.y*wv + bv;
        v.z = v.z*wv + bv; v.w = v.w*wv + bv;
        *(float4*)(base + j*1024 + t*4) = v;
    }
}

// ---------------------------------------------------------------------------
extern "C" void kernel_launch(void* const* d_in, const int* in_sizes, int n_in,
                              void* d_out, int out_size)
{
    const float* points = (const float*)d_in[0];
    const float* conv_w = (const float*)d_in[1];
    const float* conv_b = (const float*)d_in[2];
    const float* gn_w   = (const float*)d_in[3];
    const float* gn_b   = (const float*)d_in[4];
    float* out = (float*)d_out;

    conv_kernel<<<dim3(NPTS/64, NHEADS), 128>>>(points, conv_w, conv_b);
    flash_kernel<<<dim3(NQB, NHEADS), 256>>>(points, out);
    gn_apply<<<512, 256>>>(out, gn_w, gn_b);
}

// round 17
// speedup vs baseline: 1.0654x; 1.0353x over previous
#include <cuda_runtime.h>
#include <cuda_fp16.h>
#include <cstdint>
#include <math.h>

#define NB 2
#define NC 256
#define NPTS 4096
#define NG 8
#define CPG 32
#define NHEADS (NB*NG)
#define BQ 256
#define BK 128
#define NQB (NPTS/BQ)
#define NKB (NPTS/BK)

#define SBIAS  (-12.f)
#define SCLAMP 14.f

// ---------------------------------------------------------------------------
// helpers (base-target safe: sm_80-era mma.sync + cp.async + ldmatrix)
// ---------------------------------------------------------------------------
__device__ __forceinline__ uint32_t pack_f16x2(float hi, float lo) {
    uint32_t r;
    asm("cvt.rn.f16x2.f32 %0, %1, %2;" : "=r"(r) : "f"(hi), "f"(lo));
    return r;
}
__device__ __forceinline__ uint32_t ex2_h2(uint32_t a) {
    uint32_t r;
    asm("ex2.approx.f16x2 %0, %1;" : "=r"(r) : "r"(a));
    return r;
}
__device__ __forceinline__ uint32_t hmin2(uint32_t a, uint32_t b) {
    uint32_t r;
    asm("min.f16x2 %0, %1, %2;" : "=r"(r) : "r"(a), "r"(b));
    return r;
}
__device__ __forceinline__ uint32_t hadd2(uint32_t a, uint32_t b) {
    uint32_t r;
    asm("add.rn.f16x2 %0, %1, %2;" : "=r"(r) : "r"(a), "r"(b));
    return r;
}
// fp32-accumulate mma (PV, conv)
__device__ __forceinline__ void mma_fp16(float* d, const uint32_t* a,
                                         uint32_t b0, uint32_t b1) {
    asm volatile(
        "mma.sync.aligned.m16n8k16.row.col.f32.f16.f16.f32 "
        "{%0,%1,%2,%3}, {%4,%5,%6,%7}, {%8,%9}, {%0,%1,%2,%3};"
        : "+f"(d[0]), "+f"(d[1]), "+f"(d[2]), "+f"(d[3])
        : "r"(a[0]), "r"(a[1]), "r"(a[2]), "r"(a[3]), "r"(b0), "r"(b1));
}
// fp16-accumulate mma (S) — D comes out as packed f16x2 pairs
__device__ __forceinline__ void mma_h16(uint32_t* c, const uint32_t* a,
                                        uint32_t b0, uint32_t b1) {
    asm volatile(
        "mma.sync.aligned.m16n8k16.row.col.f16.f16.f16.f16 "
        "{%0,%1}, {%2,%3,%4,%5}, {%6,%7}, {%0,%1};"
        : "+r"(c[0]), "+r"(c[1])
        : "r"(a[0]), "r"(a[1]), "r"(a[2]), "r"(a[3]), "r"(b0), "r"(b1));
}
__device__ __forceinline__ uint32_t hmul2(uint32_t a, uint32_t b) {
    uint32_t r;
    asm("mul.rn.f16x2 %0, %1, %2;" : "=r"(r) : "r"(a), "r"(b));
    return r;
}
__device__ __forceinline__ void ldsm4(uint32_t* r, uint32_t addr) {
    asm volatile(
        "ldmatrix.sync.aligned.m8n8.x4.shared.b16 {%0,%1,%2,%3}, [%4];"
        : "=r"(r[0]), "=r"(r[1]), "=r"(r[2]), "=r"(r[3]) : "r"(addr));
}
__device__ __forceinline__ void cp16(uint32_t smem_dst, const void* gsrc) {
    asm volatile("cp.async.cg.shared.global [%0], [%1], 16;"
                 :: "r"(smem_dst), "l"(gsrc));
}
#define CP_COMMIT() asm volatile("cp.async.commit_group;" ::: "memory")
#define CP_WAIT_ALL() asm volatile("cp.async.wait_all;" ::: "memory")

// ---------------------------------------------------------------------------
// scratch: x fp16 [head][n][d], v = elu(x) fp16 [head][d][n]
// g_fpart: GN partials [b][group c][gh][qb][2]
// ---------------------------------------------------------------------------
__device__ __half  g_x[NHEADS*NPTS*CPG];
__device__ __half  g_v[NHEADS*CPG*NPTS];
__device__ float   g_fpart[NB*32*NG*NQB*2];

// ---------------------------------------------------------------------------
// Kernel 1: grouped 1x1 conv via tensor cores.
// X^T[n][outch] = P^T[n][inch] (A, fp16) @ W[outch][inch] (B, fp16), fp32 acc.
// Fragment patterns identical to flash: A = voff2 pattern on stride-40 [n][k]
// tile; B = koff2 pattern on stride-40 [outch][inch] (same as flash Kt).
// 64 points per CTA, grid (64, 16), 128 threads.
// ---------------------------------------------------------------------------
__global__ void __launch_bounds__(128) conv_kernel(
    const float* __restrict__ points,
    const float* __restrict__ conv_w,
    const float* __restrict__ conv_b)
{
    __shared__ __align__(16) __half Wh[32][40];    // W [outch][inch]
    __shared__ __align__(16) __half Pt[64][40];    // points^T [n][inch]; reused as xstage
    __shared__ __align__(16) __half Vst[32][72];   // v stage [ch][n]
    __shared__ float bsm[32];

    const int h = blockIdx.y;
    const int b = h >> 3, g = h & 7;
    const int t = threadIdx.x;
    const int w = t >> 5, lane = t & 31;
    const int g4 = lane >> 2, qt = lane & 3;

    // load W fp32 -> fp16 (8 per thread, coalesced)
    #pragma unroll
    for (int j = 0; j < 8; j++) {
        int i = j*128 + t;
        Wh[i >> 5][i & 31] = __float2half_rn(conv_w[g*1024 + i]);
    }
    if (t < 32) bsm[t] = conv_b[g*CPG + t];

    // load points tile [32 inch][64 n] fp32, transpose into Pt [n][inch] fp16
    {
        const float* psrc = points + (b*NC + g*CPG)*NPTS + blockIdx.x*64;
        const int irow = t >> 2, ncol = (t & 3)*16;
        #pragma unroll
        for (int j = 0; j < 4; j++) {
            float4 v4 = *(const float4*)(psrc + irow*NPTS + ncol + 4*j);
            Pt[ncol + 4*j    ][irow] = __float2half_rn(v4.x);
            Pt[ncol + 4*j + 1][irow] = __float2half_rn(v4.y);
            Pt[ncol + 4*j + 2][irow] = __float2half_rn(v4.z);
            Pt[ncol + 4*j + 3][irow] = __float2half_rn(v4.w);
        }
    }
    __syncthreads();

    // fragments
    const uint32_t aoff = (((lane & 7) + ((lane >> 3) & 1)*8)*40 + (lane >> 4)*8) * 2;
    const uint32_t boff = ((lane & 7)*40 + (lane >> 3)*8) * 2;
    uint32_t af[2][4];
    ldsm4(af[0], (uint32_t)__cvta_generic_to_shared(&Pt[w*16][0])  + aoff);
    ldsm4(af[1], (uint32_t)__cvta_generic_to_shared(&Pt[w*16][16]) + aoff);
    uint32_t bw[4][4];
    #pragma unroll
    for (int nt = 0; nt < 4; nt++)
        ldsm4(bw[nt], (uint32_t)__cvta_generic_to_shared(&Wh[nt*8][0]) + boff);

    float acc[4][4];
    #pragma unroll
    for (int nt = 0; nt < 4; nt++) {
        #pragma unroll
        for (int e = 0; e < 4; e++) acc[nt][e] = 0.f;
        mma_fp16(acc[nt], af[0], bw[nt][0], bw[nt][1]);
        mma_fp16(acc[nt], af[1], bw[nt][2], bw[nt][3]);
    }
    __syncthreads();   // all Pt reads done; safe to reuse as xstage

    // bias + x pack into Pt-as-xstage [n][chpair u32] + elu into Vst [ch][n]
    {
        const int n0 = w*16 + g4;
        #pragma unroll
        for (int nt = 0; nt < 4; nt++) {
            const int col = nt*8 + 2*qt;
            float b0 = bsm[col], b1 = bsm[col + 1];
            float c0 = acc[nt][0] + b0, c1 = acc[nt][1] + b1;
            float c2 = acc[nt][2] + b0, c3 = acc[nt][3] + b1;
            *(uint32_t*)&Pt[n0    ][col] = pack_f16x2(c1, c0);
            *(uint32_t*)&Pt[n0 + 8][col] = pack_f16x2(c3, c2);
            float e0 = c0 > 0.f ? c0 : (__expf(c0) - 1.f);
            float e1 = c1 > 0.f ? c1 : (__expf(c1) - 1.f);
            float e2 = c2 > 0.f ? c2 : (__expf(c2) - 1.f);
            float e3 = c3 > 0.f ? c3 : (__expf(c3) - 1.f);
            Vst[col    ][n0    ] = __float2half_rn(e0);
            Vst[col + 1][n0    ] = __float2half_rn(e1);
            Vst[col    ][n0 + 8] = __float2half_rn(e2);
            Vst[col + 1][n0 + 8] = __float2half_rn(e3);
        }
    }
    __syncthreads();

    // copy x: 64 n x 16 u32, coalesced
    uint32_t* gx = (uint32_t*)g_x + ((size_t)h*NPTS + blockIdx.x*64)*16;
    #pragma unroll
    for (int j = 0; j < 8; j++) {
        int m = j*128 + t;
        gx[m] = *(uint32_t*)&Pt[m >> 4][(m & 15)*2];
    }
    // copy v: 32 ch x 32 u32, coalesced per row
    uint32_t* gv = (uint32_t*)g_v + (size_t)h*CPG*NPTS/2 + blockIdx.x*32;
    #pragma unroll
    for (int j = 0; j < 8; j++) {
        int i = j*128 + t;
        int ch = i >> 5, pos = i & 31;
        gv[ch*(NPTS/2) + pos] = *(uint32_t*)&Vst[ch][pos*2];
    }
}

// ---------------------------------------------------------------------------
// Kernel 2: flash attention (R14 best: BQ=256, BK=128). S fp16-acc mma ->
// clamp+ex2 f16x2 packed; PV fp32-acc; ldmatrix; cp.async double-buffered;
// fused GN-stats epilogue. grid (16,16)=256 CTAs, 2/SM, single wave.
// ---------------------------------------------------------------------------
__global__ void __launch_bounds__(256, 2) flash_kernel(
    const float* __restrict__ points, float* __restrict__ out)
{
    __shared__ __align__(16) __half  Kt[2][128][40];   // [buf][k][d]
    __shared__ __align__(16) __half  Vs[2][32][136];   // [buf][c][k]
    __shared__ float   SL[256];
    __shared__ float   PS[8][8][4], PS2[8][8][4];      // [w][g][cidx]

    const int t = threadIdx.x, w = t >> 5, lane = t & 31;
    const int g = lane >> 2, qt = lane & 3;
    const int h = blockIdx.y, b = h >> 3, gh = h & 7;
    const int q0 = blockIdx.x * BQ;
    const __half* __restrict__ xh = g_x + (size_t)h*NPTS*CPG;
    const __half* __restrict__ vh = g_v + h*CPG*NPTS;

    const int kr = t >> 1,  kp = t & 1;
    const int vr = t >> 4,  vp = t & 15;

    __half2 c2 = __float2half2_rn(SCLAMP);
    const uint32_t clampv = *(uint32_t*)&c2;
    __half2 b2 = __float2half2_rn(SBIAS);
    const uint32_t sbias2 = *(uint32_t*)&b2;

    const uint32_t ktb0 = (uint32_t)__cvta_generic_to_shared(&Kt[0][0][0]);
    const uint32_t ktb1 = (uint32_t)__cvta_generic_to_shared(&Kt[1][0][0]);
    const uint32_t vsb0 = (uint32_t)__cvta_generic_to_shared(&Vs[0][0][0]);
    const uint32_t vsb1 = (uint32_t)__cvta_generic_to_shared(&Vs[1][0][0]);
    const uint32_t koff2 = ((lane & 7)*40 + (lane >> 3)*8) * 2;
    const uint32_t voff2 = (((lane & 7) + ((lane >> 3) & 1)*8)*136 + (lane >> 4)*8) * 2;

    // ---- Q fragments fp16, scaled by log2e/sqrt(32) ----
    uint32_t qf[2][2][4];
    {
        const uint32_t* xq = (const uint32_t*)xh;
        __half2 s2h = __float2half2_rn(0.25504526770237225f);
        uint32_t sc = *(uint32_t*)&s2h;
        #pragma unroll
        for (int qs = 0; qs < 2; qs++) {
            const int qr = q0 + 32*w + 16*qs + g;
            #pragma unroll
            for (int ds = 0; ds < 2; ds++) {
                qf[qs][ds][0] = hmul2(xq[(size_t)qr*16     + ds*8 + qt    ], sc);
                qf[qs][ds][1] = hmul2(xq[(size_t)(qr+8)*16 + ds*8 + qt    ], sc);
                qf[qs][ds][2] = hmul2(xq[(size_t)qr*16     + ds*8 + qt + 4], sc);
                qf[qs][ds][3] = hmul2(xq[(size_t)(qr+8)*16 + ds*8 + qt + 4], sc);
            }
        }
    }

    float O[2][2][2][4];
    #pragma unroll
    for (int a = 0; a < 2; a++)
        #pragma unroll
        for (int i = 0; i < 2; i++)
            #pragma unroll
            for (int j = 0; j < 2; j++)
                #pragma unroll
                for (int e = 0; e < 4; e++) O[a][i][j][e] = 0.f;
    float lsum[2][2] = {{0.f, 0.f}, {0.f, 0.f}};

    // ---- prefetch tile 0 ----
    {
        uint32_t kd = (uint32_t)__cvta_generic_to_shared(&Kt[0][kr][kp*16]);
        const __half* ksrc = xh + (size_t)kr*32 + kp*16;
        cp16(kd,      ksrc);
        cp16(kd + 16, ksrc + 8);
        #pragma unroll
        for (int j = 0; j < 2; j++) {
            int row = vr + j*16;
            uint32_t vd = (uint32_t)__cvta_generic_to_shared(&Vs[0][row][vp*8]);
            cp16(vd, vh + row*NPTS + vp*8);
        }
        CP_COMMIT();
    }

    for (int kb = 0; kb < NKB; kb++) {
        const int buf = kb & 1;
        const uint32_t ktb = buf ? ktb1 : ktb0;
        const uint32_t vsb = buf ? vsb1 : vsb0;
        CP_WAIT_ALL();
        __syncthreads();
        if (kb + 1 < NKB) {
            const int k0n = (kb + 1) * BK;
            uint32_t kd = (uint32_t)__cvta_generic_to_shared(&Kt[buf ^ 1][kr][kp*16]);
            const __half* ksrc = xh + (size_t)(k0n + kr)*32 + kp*16;
            cp16(kd,      ksrc);
            cp16(kd + 16, ksrc + 8);
            #pragma unroll
            for (int j = 0; j < 2; j++) {
                int row = vr + j*16;
                uint32_t vd = (uint32_t)__cvta_generic_to_shared(&Vs[buf ^ 1][row][vp*8]);
                cp16(vd, vh + row*NPTS + k0n + vp*8);
            }
            CP_COMMIT();
        }

        #pragma unroll
        for (int ch = 0; ch < 4; ch++) {
            uint32_t Plo[2][4], Phi[2][4];
            #pragma unroll
            for (int hf = 0; hf < 2; hf++) {
                const int kk = ch*32 + hf*16;
                uint32_t av[2][4];
                #pragma unroll
                for (int cm = 0; cm < 2; cm++)
                    ldsm4(av[cm], vsb + (uint32_t)(16*cm*136 + kk)*2 + voff2);
                #pragma unroll
                for (int nti = 0; nti < 2; nti++) {
                    const int kbase = ch*32 + (hf*2 + nti)*8;
                    uint32_t bk[4];
                    ldsm4(bk, ktb + (uint32_t)kbase*80 + koff2);
                    #pragma unroll
                    for (int qs = 0; qs < 2; qs++) {
                        uint32_t accp[2] = {sbias2, sbias2};
                        mma_h16(accp, qf[qs][0], bk[0], bk[1]);
                        mma_h16(accp, qf[qs][1], bk[2], bk[3]);
                        Plo[qs][hf*2 + nti] = ex2_h2(hmin2(accp[0], clampv));
                        Phi[qs][hf*2 + nti] = ex2_h2(hmin2(accp[1], clampv));
                    }
                }
                #pragma unroll
                for (int cm = 0; cm < 2; cm++) {
                    #pragma unroll
                    for (int qs = 0; qs < 2; qs++) {
                        mma_fp16(O[qs][cm][0], av[cm], Plo[qs][hf*2], Plo[qs][hf*2+1]);
                        mma_fp16(O[qs][cm][1], av[cm], Phi[qs][hf*2], Phi[qs][hf*2+1]);
                    }
                }
            }
            #pragma unroll
            for (int qs = 0; qs < 2; qs++) {
                uint32_t tl = hadd2(hadd2(Plo[qs][0], Plo[qs][1]),
                                    hadd2(Plo[qs][2], Plo[qs][3]));
                uint32_t th = hadd2(hadd2(Phi[qs][0], Phi[qs][1]),
                                    hadd2(Phi[qs][2], Phi[qs][3]));
                float2 fl = __half22float2(*(__half2*)&tl);
                float2 fh = __half22float2(*(__half2*)&th);
                lsum[qs][0] += fl.x + fl.y;
                lsum[qs][1] += fh.x + fh.y;
            }
        }
    }

    // ---- l[q] reduction over the quad ----
    #pragma unroll
    for (int qs = 0; qs < 2; qs++) {
        lsum[qs][0] += __shfl_xor_sync(0xffffffffu, lsum[qs][0], 1);
        lsum[qs][0] += __shfl_xor_sync(0xffffffffu, lsum[qs][0], 2);
        lsum[qs][1] += __shfl_xor_sync(0xffffffffu, lsum[qs][1], 1);
        lsum[qs][1] += __shfl_xor_sync(0xffffffffu, lsum[qs][1], 2);
    }
    __syncthreads();
    if (qt == 0) {
        #pragma unroll
        for (int qs = 0; qs < 2; qs++) {
            SL[w*32 + 16*qs + g]     = lsum[qs][0];
            SL[w*32 + 16*qs + 8 + g] = lsum[qs][1];
        }
    }
    __syncthreads();

    // ---- epilogue: divide by l, channel shuffle, residual + GN partials ----
    float cs[4] = {0.f, 0.f, 0.f, 0.f}, cs2[4] = {0.f, 0.f, 0.f, 0.f};
    #pragma unroll
    for (int qs = 0; qs < 2; qs++) {
        #pragma unroll
        for (int qh = 0; qh < 2; qh++) {
            const int qr = 16*qs + qh*8 + 2*qt;
            const float i0 = 1.f / SL[w*32 + qr];
            const float i1 = 1.f / SL[w*32 + qr + 1];
            const int q = q0 + 32*w + qr;
            #pragma unroll
            for (int cm = 0; cm < 2; cm++) {
                const int c = 16*cm + g;
                int idx = (b*NC + c*NG + gh)*NPTS + q;
                float2 r = *(const float2*)(points + idx);
                float2 o;
                o.x = O[qs][cm][qh][0]*i0 + r.x;
                o.y = O[qs][cm][qh][1]*i1 + r.y;
                *(float2*)(out + idx) = o;
                cs[2*cm]  += o.x + o.y;
                cs2[2*cm] += o.x*o.x + o.y*o.y;
                int idx2 = idx + 8*NG*NPTS;
                float2 r2 = *(const float2*)(points + idx2);
                float2 o2;
                o2.x = O[qs][cm][qh][2]*i0 + r2.x;
                o2.y = O[qs][cm][qh][3]*i1 + r2.y;
                *(float2*)(out + idx2) = o2;
                cs[2*cm+1]  += o2.x + o2.y;
                cs2[2*cm+1] += o2.x*o2.x + o2.y*o2.y;
            }
        }
    }
    #pragma unroll
    for (int i = 0; i < 4; i++) {
        cs[i]  += __shfl_xor_sync(0xffffffffu, cs[i], 1);
        cs[i]  += __shfl_xor_sync(0xffffffffu, cs[i], 2);
        cs2[i] += __shfl_xor_sync(0xffffffffu, cs2[i], 1);
        cs2[i] += __shfl_xor_sync(0xffffffffu, cs2[i], 2);
    }
    if (qt == 0) {
        #pragma unroll
        for (int i = 0; i < 4; i++) { PS[w][g][i] = cs[i]; PS2[w][g][i] = cs2[i]; }
    }
    __syncthreads();
    if (t < 32) {                       // 8 groups x 4 cidx = 32 entries
        const int gg = t >> 2, ci = t & 3;
        float s = 0.f, s2 = 0.f;
        #pragma unroll
        for (int ww = 0; ww < 8; ww++) { s += PS[ww][gg][ci]; s2 += PS2[ww][gg][ci]; }
        const int c = gg + 8*ci;        // GN group index (0..31)
        float* fp = g_fpart + ((((b*32 + c)*NG + gh)*NQB + blockIdx.x)*2);
        fp[0] = s; fp[1] = s2;
    }
}

// ---------------------------------------------------------------------------
// Kernel 3: GN apply. 512 CTAs = (b, group, slice). Deterministic reduction
// of the group's 128 flash partials (smem tree), then normalize in place.
// ---------------------------------------------------------------------------
__global__ void __launch_bounds__(256) gn_apply(
    float* __restrict__ out,
    const float* __restrict__ gn_w,
    const float* __restrict__ gn_b)
{
    __shared__ float rs[128], rs2[128];
    const int grpid = blockIdx.x >> 3, slice = blockIdx.x & 7;
    const int b = grpid >> 5, grp = grpid & 31;
    const int ch = grp*8 + slice;
    float* base = out + ((b*NC + ch)*NPTS);
    const int t = threadIdx.x;

    const float* fp = g_fpart + (size_t)grpid*NG*NQB*2;
    if (t < 128) { rs[t] = fp[2*t]; rs2[t] = fp[2*t + 1]; }
    __syncthreads();
    for (int o = 64; o; o >>= 1) {
        if (t < o) { rs[t] += rs[t+o]; rs2[t] += rs2[t+o]; }
        __syncthreads();
    }
    const float inv = 1.f / (float)(8*NPTS);
    float mean = rs[0] * inv;
    float var  = rs2[0] * inv - mean*mean;
    float rstd = rsqrtf(var + 1e-5f);
    float wv = gn_w[ch] * rstd;
    float bv = gn_b[ch] - mean * wv;

    #pragma unroll
    for (int j = 0; j < 4; j++) {
        float4 v = *(const float4*)(base + j*1024 + t*4);
        v.x = v.x*wv + bv; v.y = v.y*wv + bv;
        v.z = v.z*wv + bv; v.w = v.w*wv + bv;
        *(float4*)(base + j*1024 + t*4) = v;
    }
}

// ---------------------------------------------------------------------------
extern "C" void kernel_launch(void* const* d_in, const int* in_sizes, int n_in,
                              void* d_out, int out_size)
{
    const float* points = (const float*)d_in[0];
    const float* conv_w = (const float*)d_in[1];
    const float* conv_b = (const float*)d_in[2];
    const float* gn_w   = (const float*)d_in[3];
    const float* gn_b   = (const float*)d_in[4];
    float* out = (float*)d_out;

    conv_kernel<<<dim3(NPTS/64, NHEADS), 128>>>(points, conv_w, conv_b);
    flash_kernel<<<dim3(NQB, NHEADS), 256>>>(points, out);
    gn_apply<<<512, 256>>>(out, gn_w, gn_b);
}